// round 5
// baseline (speedup 1.0000x reference)
#include <cuda_runtime.h>
#include <cuda_fp16.h>
#include <stdint.h>

// ---------------- problem constants ----------------
#define KDIM 30000
#define MDIM 3200            // B*L
#define NDIM 1000            // Co
#define NPAD 1024
#define BDIM 32
#define CDIM 104
#define NPOOL 10

// ---------------- GEMM tiling (fp16 mma m16n8k16, fused fp32->fp16) ----------------
#define MT 128
#define NT 128
#define KB 64                             // k-values per stage
#define KSPLIT 2
#define KLEN (KDIM / KSPLIT)              // 15000
#define ITERS ((KLEN + KB - 1) / KB)      // 235 (tail 24 = 6 full float4 slots)
#define STAGES 3
#define S 72                              // padded row stride in halves (conflict-free)
#define STAGE_HALVES ((MT + NT) * S)      // 18432
#define STAGE_BYTES (STAGE_HALVES * 2)    // 36864
#define SMEM_BYTES (STAGES * STAGE_BYTES) // 110592 -> occ 2 with 128 threads

// ---------------- static scratch ----------------
__device__ float g_part[KSPLIT][(size_t)MDIM * NPAD];  // K-split partials
__device__ float g_pool[BDIM * NDIM * NPOOL];
__device__ float g_ss[BDIM * 4];                       // partial sum-of-squares
__device__ float g_fcp[4][BDIM][CDIM];                 // fc K-split partials

// ---------------- helpers ----------------
static __device__ __forceinline__ uint32_t smem_u32(const void* p) {
    uint32_t a;
    asm("{ .reg .u64 t; cvta.to.shared.u64 t, %1; cvt.u32.u64 %0, t; }" : "=r"(a) : "l"(p));
    return a;
}

#define MMA_F16(d, a, b)                                                           \
    asm volatile(                                                                  \
        "mma.sync.aligned.m16n8k16.row.col.f32.f16.f16.f32 "                       \
        "{%0,%1,%2,%3}, {%4,%5,%6,%7}, {%8,%9}, {%0,%1,%2,%3};"                    \
        : "+f"((d)[0]), "+f"((d)[1]), "+f"((d)[2]), "+f"((d)[3])                   \
        : "r"((a)[0]), "r"((a)[1]), "r"((a)[2]), "r"((a)[3]),                      \
          "r"((b)[0]), "r"((b)[1]))

// =====================================================================
// Kernel 1: GEMM partial[z][m][n] = sum_{k in split z} x[m,k]*w[n,k]
// fp16 mma m16n8k16, CTA 128x128, 4 warps of 64x64, 3-stage smem pipeline.
// Producers LDG fp32 -> cvt f16x2 -> STS fp16 (conversion fused; no scratch
// pass). 4 fetch phases per iter, each hidden behind one MMA kstep.
// grid (25, 8, 2), block 128.
// =====================================================================
__global__ void __launch_bounds__(128, 2)
gemm_kernel(const float* __restrict__ x, const float* __restrict__ w) {
    extern __shared__ __half sm[];
    const int tid = threadIdx.x;
    const int wid = tid >> 5;
    const int lane = tid & 31;
    const int g = lane >> 2;        // groupID
    const int tig = lane & 3;       // thread in group
    const int wm = wid >> 1;        // 0..1
    const int wn = wid & 1;         // 0..1
    const int m0 = blockIdx.x * MT;
    const int n0 = blockIdx.y * NT;
    const size_t zoff = (size_t)blockIdx.z * KLEN;
    const uint32_t sbase = smem_u32(sm);

    // fetch mapping: phase p, unit u: row = p*64 + u*8 + (tid>>4), slot = tid&15
    // (warp reads 2 contiguous 256B row-chunks per LDG -> 4 lines, fully coalesced;
    //  STS.64 banks: slot*2(+1) within a half-warp -> conflict-free)
    const int rsub = tid >> 4;                   // 0..7
    const int slot4 = (tid & 15) * 4;            // float offset within 64
    const uint32_t sts_off = (uint32_t)(rsub * S + slot4) * 2u;  // bytes

    const int a_row0 = wm * 64 + g;
    const int b_row0 = wn * 64 + g;

    // ---- accumulators: warp tile 64x64 = 4x8 mma tiles ----
    float acc[4][8][4];
    #pragma unroll
    for (int mt = 0; mt < 4; ++mt)
        #pragma unroll
        for (int nt = 0; nt < 8; ++nt)
            #pragma unroll
            for (int r = 0; r < 4; ++r) acc[mt][nt][r] = 0.f;

#define LDG_PHASE(p)                                                               \
    if (fetch) {                                                                   \
        _Pragma("unroll")                                                          \
        for (int u = 0; u < 8; ++u) {                                              \
            const int r_ = (p) * 64 + u * 8 + rsub;                                \
            const float* gsrc;                                                     \
            if ((p) < 2) {                                                         \
                gsrc = x + (size_t)(m0 + r_) * KDIM + zoff + kb + slot4;           \
            } else {                                                               \
                int n_ = n0 + r_ - MT;                                             \
                n_ = n_ < NDIM ? n_ : NDIM - 1;                                    \
                gsrc = w + (size_t)n_ * KDIM + zoff + kb + slot4;                  \
            }                                                                      \
            stg[u] = kin ? *(const float4*)gsrc                                    \
                         : make_float4(0.f, 0.f, 0.f, 0.f);                        \
        }                                                                          \
    }

#define STS_PHASE(p)                                                               \
    if (fetch) {                                                                   \
        _Pragma("unroll")                                                          \
        for (int u = 0; u < 8; ++u) {                                              \
            __half2 h0_ = __floats2half2_rn(stg[u].x, stg[u].y);                   \
            __half2 h1_ = __floats2half2_rn(stg[u].z, stg[u].w);                   \
            asm volatile("st.shared.v2.b32 [%0], {%1, %2};"                        \
                :: "r"(dstb + (uint32_t)(((p) * 64 + u * 8) * S * 2)),             \
                   "r"(*(uint32_t*)&h0_), "r"(*(uint32_t*)&h1_) : "memory");       \
        }                                                                          \
    }

#define KSTEP(ks)                                                                  \
    {                                                                              \
        const int kc_ = (ks) * 16 + 2 * tig;                                       \
        uint32_t af[4][4];                                                         \
        _Pragma("unroll")                                                          \
        for (int mt = 0; mt < 4; ++mt) {                                           \
            const __half* p_ = As + (a_row0 + mt * 16) * S + kc_;                  \
            af[mt][0] = *(const uint32_t*)(p_);                                    \
            af[mt][1] = *(const uint32_t*)(p_ + 8 * S);                            \
            af[mt][2] = *(const uint32_t*)(p_ + 8);                                \
            af[mt][3] = *(const uint32_t*)(p_ + 8 * S + 8);                        \
        }                                                                          \
        uint32_t bf[8][2];                                                         \
        _Pragma("unroll")                                                          \
        for (int nt = 0; nt < 8; ++nt) {                                           \
            const __half* p_ = Bs + (b_row0 + nt * 8) * S + kc_;                   \
            bf[nt][0] = *(const uint32_t*)(p_);                                    \
            bf[nt][1] = *(const uint32_t*)(p_ + 8);                                \
        }                                                                          \
        _Pragma("unroll")                                                          \
        for (int mt = 0; mt < 4; ++mt)                                             \
            _Pragma("unroll")                                                      \
            for (int nt = 0; nt < 8; ++nt)                                         \
                MMA_F16(acc[mt][nt], af[mt], bf[nt]);                              \
    }

    // ---- prologue: fetch stages 0 and 1 ----
    #pragma unroll
    for (int s = 0; s < 2; ++s) {
        const bool fetch = true;
        const bool kin = true;               // kb+slot4+4 <= 128 <= KLEN
        const int kb = s * KB;
        const uint32_t dstb = sbase + (uint32_t)s * STAGE_BYTES + sts_off;
        float4 stg[8];
        LDG_PHASE(0); STS_PHASE(0);
        LDG_PHASE(1); STS_PHASE(1);
        LDG_PHASE(2); STS_PHASE(2);
        LDG_PHASE(3); STS_PHASE(3);
    }

    // ---- main loop ----
    for (int it = 0; it < ITERS; ++it) {
        __syncthreads();
        const __half* As = sm + (size_t)(it % 3) * STAGE_HALVES;
        const __half* Bs = As + MT * S;
        const int s = it + 2;
        const bool fetch = s < ITERS;
        const int kb = s * KB;
        const bool kin = fetch && (kb + slot4 + 4 <= KLEN);
        const uint32_t dstb = sbase + (uint32_t)(s % 3) * STAGE_BYTES + sts_off;
        float4 stg[8];

        LDG_PHASE(0);
        KSTEP(0);
        STS_PHASE(0);
        LDG_PHASE(1);
        KSTEP(1);
        STS_PHASE(1);
        LDG_PHASE(2);
        KSTEP(2);
        STS_PHASE(2);
        LDG_PHASE(3);
        KSTEP(3);
        STS_PHASE(3);
    }

    // ---- epilogue: store partials (padded N => no predication) ----
    float* dst = &g_part[blockIdx.z][0];
    #pragma unroll
    for (int mt = 0; mt < 4; ++mt) {
        const int r0 = m0 + wm * 64 + mt * 16 + g;
        #pragma unroll
        for (int nt = 0; nt < 8; ++nt) {
            const int c = n0 + wn * 64 + nt * 8 + 2 * tig;
            *(float2*)&dst[(size_t)r0 * NPAD + c] =
                make_float2(acc[mt][nt][0], acc[mt][nt][1]);
            *(float2*)&dst[(size_t)(r0 + 8) * NPAD + c] =
                make_float2(acc[mt][nt][2], acc[mt][nt][3]);
        }
    }
#undef LDG_PHASE
#undef STS_PHASE
#undef KSTEP
}

// =====================================================================
// Kernel 2: bias + relu + avg-pool(10) + partial sum-of-squares
// grid (4, 32): blockIdx.x = channel quarter, blockIdx.y = batch
// =====================================================================
__global__ void __launch_bounds__(256) pool_norm_kernel(const float* __restrict__ conv_b) {
    const int q = blockIdx.x;
    const int b = blockIdx.y;
    const int tid = threadIdx.x;
    __shared__ float red[256];

    float ss = 0.f;
    if (tid < 250) {
        const int o = q * 250 + tid;
        const float bias = conv_b[o];
        float* pb = g_pool + (size_t)b * (NDIM * NPOOL) + o * NPOOL;
        #pragma unroll 2
        for (int p = 0; p < NPOOL; ++p) {
            float acc = 0.f;
            #pragma unroll
            for (int i = 0; i < 10; ++i) {
                const size_t m = (size_t)(b * 100 + p * 10 + i) * NPAD + o;
                acc += fmaxf(g_part[0][m] + g_part[1][m] + bias, 0.f);
            }
            const float v = acc * 0.1f;
            pb[p] = v;
            ss += v * v;
        }
    }
    red[tid] = ss;
    __syncthreads();
    for (int st = 128; st > 0; st >>= 1) {
        if (tid < st) red[tid] += red[tid + st];
        __syncthreads();
    }
    if (tid == 0) g_ss[b * 4 + q] = red[0];
}

// =====================================================================
// Kernel 3a: fc partials — grid (104, 4), block 128
// =====================================================================
__global__ void __launch_bounds__(128) fc_partial_kernel(const float* __restrict__ fc_w) {
    const int c = blockIdx.x;
    const int z = blockIdx.y;
    const int wid = threadIdx.x >> 5;
    const int lane = threadIdx.x & 31;
    const float4* wrow = (const float4*)(fc_w + (size_t)c * (NDIM * NPOOL) + z * 2500);

    for (int b = wid; b < BDIM; b += 4) {
        const float4* pr = (const float4*)(g_pool + (size_t)b * (NDIM * NPOOL) + z * 2500);
        float acc = 0.f;
        for (int k = lane; k < 625; k += 32) {
            float4 w4 = wrow[k];
            float4 p4 = pr[k];
            acc += w4.x * p4.x + w4.y * p4.y + w4.z * p4.z + w4.w * p4.w;
        }
        #pragma unroll
        for (int off = 16; off > 0; off >>= 1)
            acc += __shfl_xor_sync(0xFFFFFFFFu, acc, off);
        if (lane == 0) g_fcp[z][b][c] = acc;
    }
}

// =====================================================================
// Kernel 3b: finalize logits
// =====================================================================
__global__ void __launch_bounds__(256) fc_final_kernel(const float* __restrict__ fc_b,
                                                       float* __restrict__ out) {
    const int i = blockIdx.x * blockDim.x + threadIdx.x;
    if (i >= BDIM * CDIM) return;
    const int b = i / CDIM;
    const int c = i % CDIM;
    const float ss = g_ss[b * 4 + 0] + g_ss[b * 4 + 1] + g_ss[b * 4 + 2] + g_ss[b * 4 + 3];
    const float dot = g_fcp[0][b][c] + g_fcp[1][b][c] + g_fcp[2][b][c] + g_fcp[3][b][c];
    out[i] = fc_b[c] + rsqrtf(1.0f + ss) * dot;
}

// =====================================================================
extern "C" void kernel_launch(void* const* d_in, const int* in_sizes, int n_in,
                              void* d_out, int out_size) {
    const float* x      = (const float*)d_in[0];  // [32,100,30000]
    const float* conv_w = (const float*)d_in[1];  // [1000,30000]
    const float* conv_b = (const float*)d_in[2];  // [1000]
    const float* fc_w   = (const float*)d_in[3];  // [104,10000]
    const float* fc_b   = (const float*)d_in[4];  // [104]
    float* out = (float*)d_out;                   // [32,104]

    static int configured = 0;
    if (!configured) {
        cudaFuncSetAttribute(gemm_kernel,
                             cudaFuncAttributeMaxDynamicSharedMemorySize, SMEM_BYTES);
        configured = 1;
    }

    gemm_kernel<<<dim3(MDIM / MT, 8, KSPLIT), 128, SMEM_BYTES>>>(x, conv_w);
    pool_norm_kernel<<<dim3(4, BDIM), 256>>>(conv_b);
    fc_partial_kernel<<<dim3(CDIM, 4), 128>>>(fc_w);
    fc_final_kernel<<<(BDIM * CDIM + 255) / 256, 256>>>(fc_b, out);
}

// round 6
// speedup vs baseline: 1.4522x; 1.4522x over previous
#include <cuda_runtime.h>
#include <cuda_fp16.h>
#include <stdint.h>

// ---------------- problem constants ----------------
#define KDIM 30000
#define MDIM 3200            // B*L
#define NDIM 1000            // Co
#define NPAD 1024
#define BDIM 32
#define CDIM 104
#define NPOOL 10

// ---------------- GEMM tiling (fp16 mma, fp32-in-smem, consumer-side cvt) ----
#define MT 128
#define NT 128
#define KB 32                             // fp32 k-values per stage
#define KSPLIT 5
#define KLEN (KDIM / KSPLIT)              // 6000
#define ITERS ((KLEN + KB - 1) / KB)      // 188 (tail 16 floats = 4 full slots)
#define STAGES 2
#define S 40                              // padded row stride in floats
#define STAGE_FLOATS ((MT + NT) * S)      // 10240
#define STAGE_BYTES (STAGE_FLOATS * 4)    // 40960
#define SMEM_BYTES (STAGES * STAGE_BYTES) // 81920 -> occ 2 with 128 threads

// ---------------- static scratch ----------------
__device__ float g_part[KSPLIT][(size_t)MDIM * NPAD];  // K-split partials
__device__ float g_pool[BDIM * NDIM * NPOOL];
__device__ float g_ss[BDIM * 4];                       // partial sum-of-squares
__device__ float g_fcp[4][BDIM][CDIM];                 // fc K-split partials

// ---------------- helpers ----------------
static __device__ __forceinline__ uint32_t smem_u32(const void* p) {
    uint32_t a;
    asm("{ .reg .u64 t; cvta.to.shared.u64 t, %1; cvt.u32.u64 %0, t; }" : "=r"(a) : "l"(p));
    return a;
}
static __device__ __forceinline__ void cp_async16(uint32_t saddr, const void* gptr, uint32_t sz) {
    asm volatile("cp.async.cg.shared.global [%0], [%1], 16, %2;"
                 :: "r"(saddr), "l"(gptr), "r"(sz) : "memory");
}
static __device__ __forceinline__ void cp_commit() {
    asm volatile("cp.async.commit_group;" ::: "memory");
}
static __device__ __forceinline__ void cp_wait1() {
    asm volatile("cp.async.wait_group 1;" ::: "memory");
}
// fp32 pair from smem -> packed half2 register
static __device__ __forceinline__ uint32_t f2h2(const float* p) {
    float2 v = *(const float2*)p;                // LDS.64 (conflict-free @ S=40)
    __half2 h = __floats2half2_rn(v.x, v.y);     // cvt.rn.f16x2.f32
    return *(uint32_t*)&h;
}

#define MMA_F16(d, a, b)                                                           \
    asm volatile(                                                                  \
        "mma.sync.aligned.m16n8k16.row.col.f32.f16.f16.f32 "                       \
        "{%0,%1,%2,%3}, {%4,%5,%6,%7}, {%8,%9}, {%0,%1,%2,%3};"                    \
        : "+f"((d)[0]), "+f"((d)[1]), "+f"((d)[2]), "+f"((d)[3])                   \
        : "r"((a)[0]), "r"((a)[1]), "r"((a)[2]), "r"((a)[3]),                      \
          "r"((b)[0]), "r"((b)[1]))

// =====================================================================
// Kernel 1: GEMM partial[z][m][n] = sum_{k in split z} x[m,k]*w[n,k]
// fp16 mma m16n8k16; smem holds raw fp32 tiles (cp.async), fragments are
// converted fp32->half2 at LDS time. CTA 128x128, 4 warps of 64x64,
// 2-stage pipeline. grid (25, 8, 5), block 128.
// =====================================================================
__global__ void __launch_bounds__(128, 2)
gemm_kernel(const float* __restrict__ x, const float* __restrict__ w) {
    extern __shared__ float sm[];
    const int tid = threadIdx.x;
    const int wid = tid >> 5;
    const int lane = tid & 31;
    const int g = lane >> 2;        // groupID
    const int tig = lane & 3;       // thread in group
    const int wm = wid >> 1;        // 0..1
    const int wn = wid & 1;         // 0..1
    const int m0 = blockIdx.x * MT;
    const int n0 = blockIdx.y * NT;
    const size_t zoff = (size_t)blockIdx.z * KLEN;
    const uint32_t sbase = smem_u32(sm);

    // ---- per-thread cp.async items (16: 256 rows x 8 slots of 4 floats) ----
    const float* gp[16];
    uint32_t soff[16];
    int slot4[16];
    uint32_t rowok[16];
    #pragma unroll
    for (int u = 0; u < 16; ++u) {
        int i = tid + u * 128;
        int row = i >> 3;
        int slot = i & 7;
        const float* base;
        uint32_t ok = 1;
        if (row < MT) {
            base = x + (size_t)(m0 + row) * KDIM;
        } else {
            int n = n0 + row - MT;
            if (n >= NDIM) { n = NDIM - 1; ok = 0; }
            base = w + (size_t)n * KDIM;
        }
        gp[u] = base + zoff + slot * 4;
        soff[u] = (uint32_t)(row * S + slot * 4) * 4u;
        slot4[u] = slot * 4;
        rowok[u] = ok;
    }

    // tail = 16 floats = exactly 4 full 16B slots -> sz always 16 or 0
    #define ISSUE(it)                                                              \
        do {                                                                       \
            const int kb = (it) * KB;                                              \
            const int kleft = KLEN - kb;                                           \
            const uint32_t stb = sbase + ((it) & 1) * STAGE_BYTES;                 \
            _Pragma("unroll")                                                      \
            for (int u = 0; u < 16; ++u) {                                         \
                uint32_t sz = (rowok[u] && slot4[u] < kleft) ? 16u : 0u;           \
                cp_async16(stb + soff[u], gp[u] + kb, sz);                         \
            }                                                                      \
        } while (0)

    // ---- prologue: stages 0 and 1 ----
    ISSUE(0); cp_commit();
    ISSUE(1); cp_commit();

    // ---- accumulators: warp tile 64x64 = 4x8 mma tiles ----
    float acc[4][8][4];
    #pragma unroll
    for (int mt = 0; mt < 4; ++mt)
        #pragma unroll
        for (int nt = 0; nt < 8; ++nt)
            #pragma unroll
            for (int r = 0; r < 4; ++r) acc[mt][nt][r] = 0.f;

    const int a_row0 = wm * 64 + g;
    const int b_row0 = wn * 64 + g;

    // ---- main loop ----
    for (int it = 0; it < ITERS; ++it) {
        cp_wait1();
        __syncthreads();

        const float* As = sm + (it & 1) * STAGE_FLOATS;
        const float* Bs = As + MT * S;

        #pragma unroll
        for (int ks = 0; ks < 2; ++ks) {      // KB=32 -> 2 ksteps of 16
            const int kc = ks * 16 + 2 * tig;
            uint32_t af[4][4];
            #pragma unroll
            for (int mt = 0; mt < 4; ++mt) {
                const float* p = As + (a_row0 + mt * 16) * S + kc;
                af[mt][0] = f2h2(p);
                af[mt][1] = f2h2(p + 8 * S);
                af[mt][2] = f2h2(p + 8);
                af[mt][3] = f2h2(p + 8 * S + 8);
            }
            uint32_t bf[8][2];
            #pragma unroll
            for (int nt = 0; nt < 8; ++nt) {
                const float* p = Bs + (b_row0 + nt * 8) * S + kc;
                bf[nt][0] = f2h2(p);
                bf[nt][1] = f2h2(p + 8);
            }
            #pragma unroll
            for (int mt = 0; mt < 4; ++mt)
                #pragma unroll
                for (int nt = 0; nt < 8; ++nt)
                    MMA_F16(acc[mt][nt], af[mt], bf[nt]);
        }

        __syncthreads();                       // stage (it&1) free to overwrite
        if (it + 2 < ITERS) { ISSUE(it + 2); }
        cp_commit();
    }

    // ---- epilogue: store partials (padded N => no predication) ----
    float* dst = &g_part[blockIdx.z][0];
    #pragma unroll
    for (int mt = 0; mt < 4; ++mt) {
        const int r0 = m0 + wm * 64 + mt * 16 + g;
        #pragma unroll
        for (int nt = 0; nt < 8; ++nt) {
            const int c = n0 + wn * 64 + nt * 8 + 2 * tig;
            *(float2*)&dst[(size_t)r0 * NPAD + c] =
                make_float2(acc[mt][nt][0], acc[mt][nt][1]);
            *(float2*)&dst[(size_t)(r0 + 8) * NPAD + c] =
                make_float2(acc[mt][nt][2], acc[mt][nt][3]);
        }
    }
    #undef ISSUE
}

// =====================================================================
// Kernel 2: bias + relu + avg-pool(10) + partial sum-of-squares
// grid (4, 32): blockIdx.x = channel quarter, blockIdx.y = batch
// =====================================================================
__global__ void __launch_bounds__(256) pool_norm_kernel(const float* __restrict__ conv_b) {
    const int q = blockIdx.x;
    const int b = blockIdx.y;
    const int tid = threadIdx.x;
    __shared__ float red[256];

    float ss = 0.f;
    if (tid < 250) {
        const int o = q * 250 + tid;
        const float bias = conv_b[o];
        float* pb = g_pool + (size_t)b * (NDIM * NPOOL) + o * NPOOL;
        #pragma unroll 2
        for (int p = 0; p < NPOOL; ++p) {
            float acc = 0.f;
            #pragma unroll
            for (int i = 0; i < 10; ++i) {
                const size_t m = (size_t)(b * 100 + p * 10 + i) * NPAD + o;
                float v = g_part[0][m] + g_part[1][m] + g_part[2][m] +
                          g_part[3][m] + g_part[4][m] + bias;
                acc += fmaxf(v, 0.f);
            }
            const float v = acc * 0.1f;
            pb[p] = v;
            ss += v * v;
        }
    }
    red[tid] = ss;
    __syncthreads();
    for (int st = 128; st > 0; st >>= 1) {
        if (tid < st) red[tid] += red[tid + st];
        __syncthreads();
    }
    if (tid == 0) g_ss[b * 4 + q] = red[0];
}

// =====================================================================
// Kernel 3a: fc partials — grid (104, 4), block 128
// =====================================================================
__global__ void __launch_bounds__(128) fc_partial_kernel(const float* __restrict__ fc_w) {
    const int c = blockIdx.x;
    const int z = blockIdx.y;
    const int wid = threadIdx.x >> 5;
    const int lane = threadIdx.x & 31;
    const float4* wrow = (const float4*)(fc_w + (size_t)c * (NDIM * NPOOL) + z * 2500);

    for (int b = wid; b < BDIM; b += 4) {
        const float4* pr = (const float4*)(g_pool + (size_t)b * (NDIM * NPOOL) + z * 2500);
        float acc = 0.f;
        for (int k = lane; k < 625; k += 32) {
            float4 w4 = wrow[k];
            float4 p4 = pr[k];
            acc += w4.x * p4.x + w4.y * p4.y + w4.z * p4.z + w4.w * p4.w;
        }
        #pragma unroll
        for (int off = 16; off > 0; off >>= 1)
            acc += __shfl_xor_sync(0xFFFFFFFFu, acc, off);
        if (lane == 0) g_fcp[z][b][c] = acc;
    }
}

// =====================================================================
// Kernel 3b: finalize logits
// =====================================================================
__global__ void __launch_bounds__(256) fc_final_kernel(const float* __restrict__ fc_b,
                                                       float* __restrict__ out) {
    const int i = blockIdx.x * blockDim.x + threadIdx.x;
    if (i >= BDIM * CDIM) return;
    const int b = i / CDIM;
    const int c = i % CDIM;
    const float ss = g_ss[b * 4 + 0] + g_ss[b * 4 + 1] + g_ss[b * 4 + 2] + g_ss[b * 4 + 3];
    const float dot = g_fcp[0][b][c] + g_fcp[1][b][c] + g_fcp[2][b][c] + g_fcp[3][b][c];
    out[i] = fc_b[c] + rsqrtf(1.0f + ss) * dot;
}

// =====================================================================
extern "C" void kernel_launch(void* const* d_in, const int* in_sizes, int n_in,
                              void* d_out, int out_size) {
    const float* x      = (const float*)d_in[0];  // [32,100,30000]
    const float* conv_w = (const float*)d_in[1];  // [1000,30000]
    const float* conv_b = (const float*)d_in[2];  // [1000]
    const float* fc_w   = (const float*)d_in[3];  // [104,10000]
    const float* fc_b   = (const float*)d_in[4];  // [104]
    float* out = (float*)d_out;                   // [32,104]

    static int configured = 0;
    if (!configured) {
        cudaFuncSetAttribute(gemm_kernel,
                             cudaFuncAttributeMaxDynamicSharedMemorySize, SMEM_BYTES);
        configured = 1;
    }

    gemm_kernel<<<dim3(MDIM / MT, 8, KSPLIT), 128, SMEM_BYTES>>>(x, conv_w);
    pool_norm_kernel<<<dim3(4, BDIM), 256>>>(conv_b);
    fc_partial_kernel<<<dim3(CDIM, 4), 128>>>(fc_w);
    fc_final_kernel<<<(BDIM * CDIM + 255) / 256, 256>>>(fc_b, out);
}

// round 7
// speedup vs baseline: 1.6549x; 1.1396x over previous
#include <cuda_runtime.h>
#include <cuda_fp16.h>
#include <stdint.h>

// ---------------- problem constants ----------------
#define KDIM 30000
#define MDIM 3200            // B*L
#define NDIM 1000            // Co
#define NPAD 1024
#define BDIM 32
#define CDIM 104
#define NPOOL 10

// ---------------- GEMM tiling (fp16 mma m16n8k16) ----------------
#define MT 128
#define NT 128
#define KB 64                             // halves per stage
#define KSPLIT 5
#define KLEN (KDIM / KSPLIT)              // 6000
#define ITERS ((KLEN + KB - 1) / KB)      // 94 (tail 48 halves = 6 full 16B slots)
#define STAGES 3
#define S 72                              // padded row stride in halves (conflict-free)
#define STAGE_HALVES ((MT + NT) * S)      // 18432
#define STAGE_BYTES (STAGE_HALVES * 2)    // 36864
#define SMEM_BYTES (STAGES * STAGE_BYTES) // 110592 -> occ 2 with 128 threads

// ---------------- static scratch ----------------
__device__ __half g_xh[(size_t)MDIM * KDIM];           // fp16 x
__device__ __half g_wh[(size_t)NDIM * KDIM];           // fp16 conv_w
__device__ float g_part[KSPLIT][(size_t)MDIM * NPAD];  // K-split partials
__device__ float g_pool[BDIM * NDIM * NPOOL];
__device__ float g_ss[BDIM * 4];                       // partial sum-of-squares
__device__ float g_fcp[4][BDIM][CDIM];                 // fc K-split partials

// ---------------- helpers ----------------
static __device__ __forceinline__ uint32_t smem_u32(const void* p) {
    uint32_t a;
    asm("{ .reg .u64 t; cvta.to.shared.u64 t, %1; cvt.u32.u64 %0, t; }" : "=r"(a) : "l"(p));
    return a;
}
static __device__ __forceinline__ void cp_async16(uint32_t saddr, const void* gptr, uint32_t sz) {
    asm volatile("cp.async.cg.shared.global [%0], [%1], 16, %2;"
                 :: "r"(saddr), "l"(gptr), "r"(sz) : "memory");
}
static __device__ __forceinline__ void cp_commit() {
    asm volatile("cp.async.commit_group;" ::: "memory");
}
static __device__ __forceinline__ void cp_wait1() {
    asm volatile("cp.async.wait_group 1;" ::: "memory");
}

#define MMA_F16(d, a, b)                                                           \
    asm volatile(                                                                  \
        "mma.sync.aligned.m16n8k16.row.col.f32.f16.f16.f32 "                       \
        "{%0,%1,%2,%3}, {%4,%5,%6,%7}, {%8,%9}, {%0,%1,%2,%3};"                    \
        : "+f"((d)[0]), "+f"((d)[1]), "+f"((d)[2]), "+f"((d)[3])                   \
        : "r"((a)[0]), "r"((a)[1]), "r"((a)[2]), "r"((a)[3]),                      \
          "r"((b)[0]), "r"((b)[1]))

// =====================================================================
// Kernel 0: fp32 -> fp16 (rn). 8 floats -> one 16B store per thread-step.
// =====================================================================
__global__ void __launch_bounds__(256) convert_kernel(const float* __restrict__ src,
                                                      __half* __restrict__ dst, int n8) {
    int i = blockIdx.x * blockDim.x + threadIdx.x;
    const int stride = gridDim.x * blockDim.x;
    for (; i < n8; i += stride) {
        float4 v0 = ((const float4*)src)[i * 2];
        float4 v1 = ((const float4*)src)[i * 2 + 1];
        __half2 h0 = __floats2half2_rn(v0.x, v0.y);
        __half2 h1 = __floats2half2_rn(v0.z, v0.w);
        __half2 h2 = __floats2half2_rn(v1.x, v1.y);
        __half2 h3 = __floats2half2_rn(v1.z, v1.w);
        uint4 o;
        o.x = *(uint32_t*)&h0; o.y = *(uint32_t*)&h1;
        o.z = *(uint32_t*)&h2; o.w = *(uint32_t*)&h3;
        ((uint4*)dst)[i] = o;
    }
}

// =====================================================================
// Kernel 1: GEMM partial[z][m][n] = sum_{k in split z} x[m,k]*w[n,k]
// fp16 mma.sync m16n8k16, CTA 128x128, 4 warps of 64x64, 3-stage cp.async.
// grid (25, 8, 5), block 128.  (R4-proven mainloop; only KSPLIT changed.)
// =====================================================================
__global__ void __launch_bounds__(128, 2)
gemm_kernel() {
    extern __shared__ __half sm[];
    const int tid = threadIdx.x;
    const int wid = tid >> 5;
    const int lane = tid & 31;
    const int g = lane >> 2;        // groupID
    const int tig = lane & 3;       // thread in group
    const int wm = wid >> 1;        // 0..1
    const int wn = wid & 1;         // 0..1
    const int m0 = blockIdx.x * MT;
    const int n0 = blockIdx.y * NT;
    const int z = blockIdx.z;
    const uint32_t sbase = smem_u32(sm);

    // ---- per-thread cp.async items (16: 256 rows x 8 slots of 8 halves) ----
    const __half* gp[16];
    uint32_t soff[16];
    int slot8[16];
    uint32_t rowok[16];
    #pragma unroll
    for (int u = 0; u < 16; ++u) {
        int i = tid + u * 128;
        int row = i >> 3;
        int slot = i & 7;
        const __half* base;
        uint32_t ok = 1;
        if (row < MT) {
            base = g_xh + (size_t)(m0 + row) * KDIM;
        } else {
            int n = n0 + row - MT;
            if (n >= NDIM) { n = NDIM - 1; ok = 0; }
            base = g_wh + (size_t)n * KDIM;
        }
        gp[u] = base + (size_t)z * KLEN + slot * 8;
        soff[u] = (uint32_t)(row * S + slot * 8) * 2u;
        slot8[u] = slot * 8;
        rowok[u] = ok;
    }

    // tail = 48 halves = exactly 6 full 16B slots -> sz always 16 or 0
    // (cp.async src-size 0 zero-fills the 16B destination)
    #define ISSUE(it)                                                              \
        do {                                                                       \
            const int kb = (it) * KB;                                              \
            const int kleft = KLEN - kb;                                           \
            const uint32_t stb = sbase + ((it) % STAGES) * STAGE_BYTES;            \
            _Pragma("unroll")                                                      \
            for (int u = 0; u < 16; ++u) {                                         \
                uint32_t sz = (rowok[u] && slot8[u] < kleft) ? 16u : 0u;           \
                cp_async16(stb + soff[u], gp[u] + kb, sz);                         \
            }                                                                      \
        } while (0)

    // ---- prologue ----
    ISSUE(0); cp_commit();
    ISSUE(1); cp_commit();

    // ---- accumulators: warp tile 64x64 = 4x8 mma tiles ----
    float acc[4][8][4];
    #pragma unroll
    for (int mt = 0; mt < 4; ++mt)
        #pragma unroll
        for (int nt = 0; nt < 8; ++nt)
            #pragma unroll
            for (int r = 0; r < 4; ++r) acc[mt][nt][r] = 0.f;

    const int a_row0 = wm * 64 + g;
    const int b_row0 = wn * 64 + g;

    // ---- main loop ----
    for (int it = 0; it < ITERS; ++it) {
        cp_wait1();
        __syncthreads();
        if (it + 2 < ITERS) { ISSUE(it + 2); }
        cp_commit();

        const __half* As = sm + ((size_t)(it % STAGES)) * STAGE_HALVES;
        const __half* Bs = As + MT * S;

        #pragma unroll
        for (int ks = 0; ks < 4; ++ks) {
            const int kc = ks * 16 + 2 * tig;
            uint32_t af[4][4];
            #pragma unroll
            for (int mt = 0; mt < 4; ++mt) {
                const __half* p = As + (a_row0 + mt * 16) * S + kc;
                af[mt][0] = *(const uint32_t*)(p);
                af[mt][1] = *(const uint32_t*)(p + 8 * S);
                af[mt][2] = *(const uint32_t*)(p + 8);
                af[mt][3] = *(const uint32_t*)(p + 8 * S + 8);
            }
            uint32_t bf[8][2];
            #pragma unroll
            for (int nt = 0; nt < 8; ++nt) {
                const __half* p = Bs + (b_row0 + nt * 8) * S + kc;
                bf[nt][0] = *(const uint32_t*)(p);
                bf[nt][1] = *(const uint32_t*)(p + 8);
            }
            #pragma unroll
            for (int mt = 0; mt < 4; ++mt)
                #pragma unroll
                for (int nt = 0; nt < 8; ++nt)
                    MMA_F16(acc[mt][nt], af[mt], bf[nt]);
        }
    }

    // ---- epilogue: store partials (padded N => no predication) ----
    float* dst = &g_part[z][0];
    #pragma unroll
    for (int mt = 0; mt < 4; ++mt) {
        const int r0 = m0 + wm * 64 + mt * 16 + g;
        #pragma unroll
        for (int nt = 0; nt < 8; ++nt) {
            const int c = n0 + wn * 64 + nt * 8 + 2 * tig;
            *(float2*)&dst[(size_t)r0 * NPAD + c] =
                make_float2(acc[mt][nt][0], acc[mt][nt][1]);
            *(float2*)&dst[(size_t)(r0 + 8) * NPAD + c] =
                make_float2(acc[mt][nt][2], acc[mt][nt][3]);
        }
    }
    #undef ISSUE
}

// =====================================================================
// Kernel 2: bias + relu + avg-pool(10) + partial sum-of-squares
// grid (4, 32): blockIdx.x = channel quarter, blockIdx.y = batch
// =====================================================================
__global__ void __launch_bounds__(256) pool_norm_kernel(const float* __restrict__ conv_b) {
    const int q = blockIdx.x;
    const int b = blockIdx.y;
    const int tid = threadIdx.x;
    __shared__ float red[256];

    float ss = 0.f;
    if (tid < 250) {
        const int o = q * 250 + tid;
        const float bias = conv_b[o];
        float* pb = g_pool + (size_t)b * (NDIM * NPOOL) + o * NPOOL;
        #pragma unroll 2
        for (int p = 0; p < NPOOL; ++p) {
            float acc = 0.f;
            #pragma unroll
            for (int i = 0; i < 10; ++i) {
                const size_t m = (size_t)(b * 100 + p * 10 + i) * NPAD + o;
                float v = g_part[0][m] + g_part[1][m] + g_part[2][m] +
                          g_part[3][m] + g_part[4][m] + bias;
                acc += fmaxf(v, 0.f);
            }
            const float v = acc * 0.1f;
            pb[p] = v;
            ss += v * v;
        }
    }
    red[tid] = ss;
    __syncthreads();
    for (int st = 128; st > 0; st >>= 1) {
        if (tid < st) red[tid] += red[tid + st];
        __syncthreads();
    }
    if (tid == 0) g_ss[b * 4 + q] = red[0];
}

// =====================================================================
// Kernel 3a: fc partials — grid (104, 4), block 128
// =====================================================================
__global__ void __launch_bounds__(128) fc_partial_kernel(const float* __restrict__ fc_w) {
    const int c = blockIdx.x;
    const int z = blockIdx.y;
    const int wid = threadIdx.x >> 5;
    const int lane = threadIdx.x & 31;
    const float4* wrow = (const float4*)(fc_w + (size_t)c * (NDIM * NPOOL) + z * 2500);

    for (int b = wid; b < BDIM; b += 4) {
        const float4* pr = (const float4*)(g_pool + (size_t)b * (NDIM * NPOOL) + z * 2500);
        float acc = 0.f;
        for (int k = lane; k < 625; k += 32) {
            float4 w4 = wrow[k];
            float4 p4 = pr[k];
            acc += w4.x * p4.x + w4.y * p4.y + w4.z * p4.z + w4.w * p4.w;
        }
        #pragma unroll
        for (int off = 16; off > 0; off >>= 1)
            acc += __shfl_xor_sync(0xFFFFFFFFu, acc, off);
        if (lane == 0) g_fcp[z][b][c] = acc;
    }
}

// =====================================================================
// Kernel 3b: finalize logits
// =====================================================================
__global__ void __launch_bounds__(256) fc_final_kernel(const float* __restrict__ fc_b,
                                                       float* __restrict__ out) {
    const int i = blockIdx.x * blockDim.x + threadIdx.x;
    if (i >= BDIM * CDIM) return;
    const int b = i / CDIM;
    const int c = i % CDIM;
    const float ss = g_ss[b * 4 + 0] + g_ss[b * 4 + 1] + g_ss[b * 4 + 2] + g_ss[b * 4 + 3];
    const float dot = g_fcp[0][b][c] + g_fcp[1][b][c] + g_fcp[2][b][c] + g_fcp[3][b][c];
    out[i] = fc_b[c] + rsqrtf(1.0f + ss) * dot;
}

// =====================================================================
extern "C" void kernel_launch(void* const* d_in, const int* in_sizes, int n_in,
                              void* d_out, int out_size) {
    const float* x      = (const float*)d_in[0];  // [32,100,30000]
    const float* conv_w = (const float*)d_in[1];  // [1000,30000]
    const float* conv_b = (const float*)d_in[2];  // [1000]
    const float* fc_w   = (const float*)d_in[3];  // [104,10000]
    const float* fc_b   = (const float*)d_in[4];  // [104]
    float* out = (float*)d_out;                   // [32,104]

    static int configured = 0;
    if (!configured) {
        cudaFuncSetAttribute(gemm_kernel,
                             cudaFuncAttributeMaxDynamicSharedMemorySize, SMEM_BYTES);
        configured = 1;
    }

    __half* xh; cudaGetSymbolAddress((void**)&xh, g_xh);
    __half* wh; cudaGetSymbolAddress((void**)&wh, g_wh);

    convert_kernel<<<2048, 256>>>(x, xh, (MDIM * KDIM) / 8);
    convert_kernel<<<1024, 256>>>(conv_w, wh, (NDIM * KDIM) / 8);
    gemm_kernel<<<dim3(MDIM / MT, 8, KSPLIT), 128, SMEM_BYTES>>>();
    pool_norm_kernel<<<dim3(4, BDIM), 256>>>(conv_b);
    fc_partial_kernel<<<dim3(CDIM, 4), 128>>>(fc_w);
    fc_final_kernel<<<(BDIM * CDIM + 255) / 256, 256>>>(fc_b, out);
}

// round 9
// speedup vs baseline: 1.6742x; 1.0116x over previous
#include <cuda_runtime.h>
#include <cuda_fp16.h>
#include <stdint.h>

// ---------------- problem constants ----------------
#define KDIM 30000
#define MDIM 3200            // B*L
#define NDIM 1000            // Co
#define NPAD 1024
#define BDIM 32
#define CDIM 104
#define NPOOL 10

// ---------------- GEMM tiling (fp16 mma m16n8k16) ----------------
#define MT 128
#define NT 128
#define KB 64                             // halves per stage
#define KSPLIT 5
#define KLEN (KDIM / KSPLIT)              // 6000
#define ITERS ((KLEN + KB - 1) / KB)      // 94 (tail 48 halves = 6 full 16B slots)
#define STAGES 3
#define S 72                              // padded row stride in halves (conflict-free)
#define STAGE_HALVES ((MT + NT) * S)      // 18432
#define STAGE_BYTES (STAGE_HALVES * 2)    // 36864
#define SMEM_BYTES (STAGES * STAGE_BYTES) // 110592 -> occ 2 with 128 threads

// ---------------- static scratch ----------------
__device__ __half g_xh[(size_t)MDIM * KDIM];           // fp16 x
__device__ __half g_wh[(size_t)NDIM * KDIM];           // fp16 conv_w
__device__ float g_part[KSPLIT][(size_t)MDIM * NPAD];  // K-split partials
__device__ float g_pool[BDIM * NDIM * NPOOL];
__device__ float g_ss[BDIM * 40];                      // sum-of-squares partials (q,p)

// ---------------- helpers ----------------
static __device__ __forceinline__ uint32_t smem_u32(const void* p) {
    uint32_t a;
    asm("{ .reg .u64 t; cvta.to.shared.u64 t, %1; cvt.u32.u64 %0, t; }" : "=r"(a) : "l"(p));
    return a;
}
static __device__ __forceinline__ void cp_async16(uint32_t saddr, const void* gptr, uint32_t sz) {
    asm volatile("cp.async.cg.shared.global [%0], [%1], 16, %2;"
                 :: "r"(saddr), "l"(gptr), "r"(sz) : "memory");
}
static __device__ __forceinline__ void cp_commit() {
    asm volatile("cp.async.commit_group;" ::: "memory");
}
static __device__ __forceinline__ void cp_wait1() {
    asm volatile("cp.async.wait_group 1;" ::: "memory");
}

#define MMA_F16(d, a, b)                                                           \
    asm volatile(                                                                  \
        "mma.sync.aligned.m16n8k16.row.col.f32.f16.f16.f32 "                       \
        "{%0,%1,%2,%3}, {%4,%5,%6,%7}, {%8,%9}, {%0,%1,%2,%3};"                    \
        : "+f"((d)[0]), "+f"((d)[1]), "+f"((d)[2]), "+f"((d)[3])                   \
        : "r"((a)[0]), "r"((a)[1]), "r"((a)[2]), "r"((a)[3]),                      \
          "r"((b)[0]), "r"((b)[1]))

// =====================================================================
// Kernel 0: fp32 -> fp16 (rn) for x and conv_w in ONE launch.
// Virtual index space: [0, nx8 + nw8) of 8-float groups.
// =====================================================================
__global__ void __launch_bounds__(256) convert_kernel(const float* __restrict__ x,
                                                      const float* __restrict__ w,
                                                      __half* __restrict__ xh,
                                                      __half* __restrict__ wh,
                                                      int nx8, int ntot8) {
    int i = blockIdx.x * blockDim.x + threadIdx.x;
    const int stride = gridDim.x * blockDim.x;
    for (; i < ntot8; i += stride) {
        const float* src;
        __half* dst;
        int j;
        if (i < nx8) { src = x; dst = xh; j = i; }
        else         { src = w; dst = wh; j = i - nx8; }
        float4 v0 = ((const float4*)src)[j * 2];
        float4 v1 = ((const float4*)src)[j * 2 + 1];
        __half2 h0 = __floats2half2_rn(v0.x, v0.y);
        __half2 h1 = __floats2half2_rn(v0.z, v0.w);
        __half2 h2 = __floats2half2_rn(v1.x, v1.y);
        __half2 h3 = __floats2half2_rn(v1.z, v1.w);
        uint4 o;
        o.x = *(uint32_t*)&h0; o.y = *(uint32_t*)&h1;
        o.z = *(uint32_t*)&h2; o.w = *(uint32_t*)&h3;
        ((uint4*)dst)[j] = o;
    }
}

// =====================================================================
// Kernel 1: GEMM partial[z][m][n] = sum_{k in split z} x[m,k]*w[n,k]
// fp16 mma.sync m16n8k16, CTA 128x128, 4 warps of 64x64, 3-stage cp.async.
// grid (25, 8, 5), block 128.  (R7-proven; unchanged.)
// =====================================================================
__global__ void __launch_bounds__(128, 2)
gemm_kernel() {
    extern __shared__ __half sm[];
    const int tid = threadIdx.x;
    const int wid = tid >> 5;
    const int lane = tid & 31;
    const int g = lane >> 2;        // groupID
    const int tig = lane & 3;       // thread in group
    const int wm = wid >> 1;        // 0..1
    const int wn = wid & 1;         // 0..1
    const int m0 = blockIdx.x * MT;
    const int n0 = blockIdx.y * NT;
    const int z = blockIdx.z;
    const uint32_t sbase = smem_u32(sm);

    // ---- per-thread cp.async items (16: 256 rows x 8 slots of 8 halves) ----
    const __half* gp[16];
    uint32_t soff[16];
    int slot8[16];
    uint32_t rowok[16];
    #pragma unroll
    for (int u = 0; u < 16; ++u) {
        int i = tid + u * 128;
        int row = i >> 3;
        int slot = i & 7;
        const __half* base;
        uint32_t ok = 1;
        if (row < MT) {
            base = g_xh + (size_t)(m0 + row) * KDIM;
        } else {
            int n = n0 + row - MT;
            if (n >= NDIM) { n = NDIM - 1; ok = 0; }
            base = g_wh + (size_t)n * KDIM;
        }
        gp[u] = base + (size_t)z * KLEN + slot * 8;
        soff[u] = (uint32_t)(row * S + slot * 8) * 2u;
        slot8[u] = slot * 8;
        rowok[u] = ok;
    }

    // tail = 48 halves = exactly 6 full 16B slots -> sz always 16 or 0
    #define ISSUE(it)                                                              \
        do {                                                                       \
            const int kb = (it) * KB;                                              \
            const int kleft = KLEN - kb;                                           \
            const uint32_t stb = sbase + ((it) % STAGES) * STAGE_BYTES;            \
            _Pragma("unroll")                                                      \
            for (int u = 0; u < 16; ++u) {                                         \
                uint32_t sz = (rowok[u] && slot8[u] < kleft) ? 16u : 0u;           \
                cp_async16(stb + soff[u], gp[u] + kb, sz);                         \
            }                                                                      \
        } while (0)

    // ---- prologue ----
    ISSUE(0); cp_commit();
    ISSUE(1); cp_commit();

    // ---- accumulators: warp tile 64x64 = 4x8 mma tiles ----
    float acc[4][8][4];
    #pragma unroll
    for (int mt = 0; mt < 4; ++mt)
        #pragma unroll
        for (int nt = 0; nt < 8; ++nt)
            #pragma unroll
            for (int r = 0; r < 4; ++r) acc[mt][nt][r] = 0.f;

    const int a_row0 = wm * 64 + g;
    const int b_row0 = wn * 64 + g;

    // ---- main loop ----
    for (int it = 0; it < ITERS; ++it) {
        cp_wait1();
        __syncthreads();
        if (it + 2 < ITERS) { ISSUE(it + 2); }
        cp_commit();

        const __half* As = sm + ((size_t)(it % STAGES)) * STAGE_HALVES;
        const __half* Bs = As + MT * S;

        #pragma unroll
        for (int ks = 0; ks < 4; ++ks) {
            const int kc = ks * 16 + 2 * tig;
            uint32_t af[4][4];
            #pragma unroll
            for (int mt = 0; mt < 4; ++mt) {
                const __half* p = As + (a_row0 + mt * 16) * S + kc;
                af[mt][0] = *(const uint32_t*)(p);
                af[mt][1] = *(const uint32_t*)(p + 8 * S);
                af[mt][2] = *(const uint32_t*)(p + 8);
                af[mt][3] = *(const uint32_t*)(p + 8 * S + 8);
            }
            uint32_t bf[8][2];
            #pragma unroll
            for (int nt = 0; nt < 8; ++nt) {
                const __half* p = Bs + (b_row0 + nt * 8) * S + kc;
                bf[nt][0] = *(const uint32_t*)(p);
                bf[nt][1] = *(const uint32_t*)(p + 8);
            }
            #pragma unroll
            for (int mt = 0; mt < 4; ++mt)
                #pragma unroll
                for (int nt = 0; nt < 8; ++nt)
                    MMA_F16(acc[mt][nt], af[mt], bf[nt]);
        }
    }

    // ---- epilogue: store partials (padded N => no predication) ----
    float* dst = &g_part[z][0];
    #pragma unroll
    for (int mt = 0; mt < 4; ++mt) {
        const int r0 = m0 + wm * 64 + mt * 16 + g;
        #pragma unroll
        for (int nt = 0; nt < 8; ++nt) {
            const int c = n0 + wn * 64 + nt * 8 + 2 * tig;
            *(float2*)&dst[(size_t)r0 * NPAD + c] =
                make_float2(acc[mt][nt][0], acc[mt][nt][1]);
            *(float2*)&dst[(size_t)(r0 + 8) * NPAD + c] =
                make_float2(acc[mt][nt][2], acc[mt][nt][3]);
        }
    }
    #undef ISSUE
}

// =====================================================================
// Kernel 2: bias + relu + avg-pool(10) + partial sum-of-squares
// grid (4, 32, 10): (channel quarter q, batch b, pool window p)
// =====================================================================
__global__ void __launch_bounds__(256) pool_norm_kernel(const float* __restrict__ conv_b) {
    const int q = blockIdx.x;
    const int b = blockIdx.y;
    const int p = blockIdx.z;
    const int tid = threadIdx.x;
    __shared__ float red[256];

    float ss = 0.f;
    if (tid < 250) {
        const int o = q * 250 + tid;
        const float bias = conv_b[o];
        float acc = 0.f;
        #pragma unroll
        for (int i = 0; i < 10; ++i) {
            const size_t m = (size_t)(b * 100 + p * 10 + i) * NPAD + o;
            float v = g_part[0][m] + g_part[1][m] + g_part[2][m] +
                      g_part[3][m] + g_part[4][m] + bias;
            acc += fmaxf(v, 0.f);
        }
        const float v = acc * 0.1f;
        g_pool[(size_t)b * (NDIM * NPOOL) + o * NPOOL + p] = v;
        ss = v * v;
    }
    red[tid] = ss;
    __syncthreads();
    for (int st = 128; st > 0; st >>= 1) {
        if (tid < st) red[tid] += red[tid + st];
        __syncthreads();
    }
    if (tid == 0) g_ss[b * 40 + q * 10 + p] = red[0];
}

// =====================================================================
// Kernel 3: logits — grid 104, block 256 (8 warps x 4 batches each)
// per-batch ss summed once into smem, rsqrt folded into the dot.
// =====================================================================
__global__ void __launch_bounds__(256) fc_kernel(const float* __restrict__ fc_w,
                                                 const float* __restrict__ fc_b,
                                                 float* __restrict__ out) {
    const int c = blockIdx.x;
    const int tid = threadIdx.x;
    __shared__ float ssb[BDIM];

    if (tid < BDIM) {
        float s = 0.f;
        #pragma unroll
        for (int j = 0; j < 40; ++j) s += g_ss[tid * 40 + j];
        ssb[tid] = rsqrtf(1.0f + s);
    }
    __syncthreads();

    const int wid = tid >> 5;
    const int lane = tid & 31;
    const float4* wrow = (const float4*)(fc_w + (size_t)c * (NDIM * NPOOL));
    const float bias = fc_b[c];

    for (int b = wid; b < BDIM; b += 8) {
        const float4* pr = (const float4*)(g_pool + (size_t)b * (NDIM * NPOOL));
        float acc = 0.f;
        for (int k = lane; k < (NDIM * NPOOL) / 4; k += 32) {
            float4 w4 = wrow[k];
            float4 p4 = pr[k];
            acc += w4.x * p4.x + w4.y * p4.y + w4.z * p4.z + w4.w * p4.w;
        }
        #pragma unroll
        for (int off = 16; off > 0; off >>= 1)
            acc += __shfl_xor_sync(0xFFFFFFFFu, acc, off);
        if (lane == 0) out[b * CDIM + c] = bias + ssb[b] * acc;
    }
}

// =====================================================================
extern "C" void kernel_launch(void* const* d_in, const int* in_sizes, int n_in,
                              void* d_out, int out_size) {
    const float* x      = (const float*)d_in[0];  // [32,100,30000]
    const float* conv_w = (const float*)d_in[1];  // [1000,30000]
    const float* conv_b = (const float*)d_in[2];  // [1000]
    const float* fc_w   = (const float*)d_in[3];  // [104,10000]
    const float* fc_b   = (const float*)d_in[4];  // [104]
    float* out = (float*)d_out;                   // [32,104]

    static int configured = 0;
    if (!configured) {
        cudaFuncSetAttribute(gemm_kernel,
                             cudaFuncAttributeMaxDynamicSharedMemorySize, SMEM_BYTES);
        configured = 1;
    }

    __half* xh; cudaGetSymbolAddress((void**)&xh, g_xh);
    __half* wh; cudaGetSymbolAddress((void**)&wh, g_wh);

    const int nx8 = (MDIM * KDIM) / 8;
    const int ntot8 = nx8 + (NDIM * KDIM) / 8;
    convert_kernel<<<3072, 256>>>(x, conv_w, xh, wh, nx8, ntot8);
    gemm_kernel<<<dim3(MDIM / MT, 8, KSPLIT), 128, SMEM_BYTES>>>();
    pool_norm_kernel<<<dim3(4, BDIM, NPOOL), 256>>>(conv_b);
    fc_kernel<<<CDIM, 256>>>(fc_w, fc_b, out);
}

// round 10
// speedup vs baseline: 1.7530x; 1.0471x over previous
#include <cuda_runtime.h>
#include <cuda_fp16.h>
#include <stdint.h>

// ---------------- problem constants ----------------
#define KDIM 30000
#define MDIM 3200            // B*L
#define NDIM 1000            // Co
#define NPAD 1024
#define BDIM 32
#define CDIM 104
#define NPOOL 10
#define FCZ 5                // fc K-split (10000 = 5 * 2000)

// ---------------- GEMM tiling (fp16 mma m16n8k16) ----------------
#define MT 128
#define NT 128
#define KB 64                             // halves per stage
#define KSPLIT 5
#define KLEN (KDIM / KSPLIT)              // 6000
#define ITERS ((KLEN + KB - 1) / KB)      // 94 (tail 48 halves = 6 full 16B slots)
#define STAGES 3
#define S 72                              // padded row stride in halves (conflict-free)
#define STAGE_HALVES ((MT + NT) * S)      // 18432
#define STAGE_BYTES (STAGE_HALVES * 2)    // 36864
#define SMEM_BYTES (STAGES * STAGE_BYTES) // 110592 -> occ 2 with 128 threads

// ---------------- static scratch ----------------
__device__ __half g_xh[(size_t)MDIM * KDIM];           // fp16 x
__device__ __half g_wh[(size_t)NDIM * KDIM];           // fp16 conv_w
__device__ float g_part[KSPLIT][(size_t)MDIM * NPAD];  // K-split partials
__device__ float g_pool[BDIM * NDIM * NPOOL];
__device__ float g_ss[BDIM * 40];                      // sum-of-squares partials (q,p)
__device__ float g_fcp[FCZ][BDIM][CDIM];               // fc K-split partials

// ---------------- helpers ----------------
static __device__ __forceinline__ uint32_t smem_u32(const void* p) {
    uint32_t a;
    asm("{ .reg .u64 t; cvta.to.shared.u64 t, %1; cvt.u32.u64 %0, t; }" : "=r"(a) : "l"(p));
    return a;
}
static __device__ __forceinline__ void cp_async16(uint32_t saddr, const void* gptr, uint32_t sz) {
    asm volatile("cp.async.cg.shared.global [%0], [%1], 16, %2;"
                 :: "r"(saddr), "l"(gptr), "r"(sz) : "memory");
}
static __device__ __forceinline__ void cp_commit() {
    asm volatile("cp.async.commit_group;" ::: "memory");
}
static __device__ __forceinline__ void cp_wait1() {
    asm volatile("cp.async.wait_group 1;" ::: "memory");
}

#define MMA_F16(d, a, b)                                                           \
    asm volatile(                                                                  \
        "mma.sync.aligned.m16n8k16.row.col.f32.f16.f16.f32 "                       \
        "{%0,%1,%2,%3}, {%4,%5,%6,%7}, {%8,%9}, {%0,%1,%2,%3};"                    \
        : "+f"((d)[0]), "+f"((d)[1]), "+f"((d)[2]), "+f"((d)[3])                   \
        : "r"((a)[0]), "r"((a)[1]), "r"((a)[2]), "r"((a)[3]),                      \
          "r"((b)[0]), "r"((b)[1]))

// =====================================================================
// Kernel 0: fp32 -> fp16 (rn) for x and conv_w in ONE launch.
// =====================================================================
__global__ void __launch_bounds__(256) convert_kernel(const float* __restrict__ x,
                                                      const float* __restrict__ w,
                                                      __half* __restrict__ xh,
                                                      __half* __restrict__ wh,
                                                      int nx8, int ntot8) {
    int i = blockIdx.x * blockDim.x + threadIdx.x;
    const int stride = gridDim.x * blockDim.x;
    for (; i < ntot8; i += stride) {
        const float* src;
        __half* dst;
        int j;
        if (i < nx8) { src = x; dst = xh; j = i; }
        else         { src = w; dst = wh; j = i - nx8; }
        float4 v0 = ((const float4*)src)[j * 2];
        float4 v1 = ((const float4*)src)[j * 2 + 1];
        __half2 h0 = __floats2half2_rn(v0.x, v0.y);
        __half2 h1 = __floats2half2_rn(v0.z, v0.w);
        __half2 h2 = __floats2half2_rn(v1.x, v1.y);
        __half2 h3 = __floats2half2_rn(v1.z, v1.w);
        uint4 o;
        o.x = *(uint32_t*)&h0; o.y = *(uint32_t*)&h1;
        o.z = *(uint32_t*)&h2; o.w = *(uint32_t*)&h3;
        ((uint4*)dst)[j] = o;
    }
}

// =====================================================================
// Kernel 1: GEMM partial[z][m][n] = sum_{k in split z} x[m,k]*w[n,k]
// fp16 mma.sync m16n8k16, CTA 128x128, 4 warps of 64x64, 3-stage cp.async.
// grid (25, 8, 5), block 128.  (Proven mainloop; unchanged.)
// =====================================================================
__global__ void __launch_bounds__(128, 2)
gemm_kernel() {
    extern __shared__ __half sm[];
    const int tid = threadIdx.x;
    const int wid = tid >> 5;
    const int lane = tid & 31;
    const int g = lane >> 2;        // groupID
    const int tig = lane & 3;       // thread in group
    const int wm = wid >> 1;        // 0..1
    const int wn = wid & 1;         // 0..1
    const int m0 = blockIdx.x * MT;
    const int n0 = blockIdx.y * NT;
    const int z = blockIdx.z;
    const uint32_t sbase = smem_u32(sm);

    // ---- per-thread cp.async items (16: 256 rows x 8 slots of 8 halves) ----
    const __half* gp[16];
    uint32_t soff[16];
    int slot8[16];
    uint32_t rowok[16];
    #pragma unroll
    for (int u = 0; u < 16; ++u) {
        int i = tid + u * 128;
        int row = i >> 3;
        int slot = i & 7;
        const __half* base;
        uint32_t ok = 1;
        if (row < MT) {
            base = g_xh + (size_t)(m0 + row) * KDIM;
        } else {
            int n = n0 + row - MT;
            if (n >= NDIM) { n = NDIM - 1; ok = 0; }
            base = g_wh + (size_t)n * KDIM;
        }
        gp[u] = base + (size_t)z * KLEN + slot * 8;
        soff[u] = (uint32_t)(row * S + slot * 8) * 2u;
        slot8[u] = slot * 8;
        rowok[u] = ok;
    }

    // tail = 48 halves = exactly 6 full 16B slots -> sz always 16 or 0
    #define ISSUE(it)                                                              \
        do {                                                                       \
            const int kb = (it) * KB;                                              \
            const int kleft = KLEN - kb;                                           \
            const uint32_t stb = sbase + ((it) % STAGES) * STAGE_BYTES;            \
            _Pragma("unroll")                                                      \
            for (int u = 0; u < 16; ++u) {                                         \
                uint32_t sz = (rowok[u] && slot8[u] < kleft) ? 16u : 0u;           \
                cp_async16(stb + soff[u], gp[u] + kb, sz);                         \
            }                                                                      \
        } while (0)

    // ---- prologue ----
    ISSUE(0); cp_commit();
    ISSUE(1); cp_commit();

    // ---- accumulators: warp tile 64x64 = 4x8 mma tiles ----
    float acc[4][8][4];
    #pragma unroll
    for (int mt = 0; mt < 4; ++mt)
        #pragma unroll
        for (int nt = 0; nt < 8; ++nt)
            #pragma unroll
            for (int r = 0; r < 4; ++r) acc[mt][nt][r] = 0.f;

    const int a_row0 = wm * 64 + g;
    const int b_row0 = wn * 64 + g;

    // ---- main loop ----
    for (int it = 0; it < ITERS; ++it) {
        cp_wait1();
        __syncthreads();
        if (it + 2 < ITERS) { ISSUE(it + 2); }
        cp_commit();

        const __half* As = sm + ((size_t)(it % STAGES)) * STAGE_HALVES;
        const __half* Bs = As + MT * S;

        #pragma unroll
        for (int ks = 0; ks < 4; ++ks) {
            const int kc = ks * 16 + 2 * tig;
            uint32_t af[4][4];
            #pragma unroll
            for (int mt = 0; mt < 4; ++mt) {
                const __half* p = As + (a_row0 + mt * 16) * S + kc;
                af[mt][0] = *(const uint32_t*)(p);
                af[mt][1] = *(const uint32_t*)(p + 8 * S);
                af[mt][2] = *(const uint32_t*)(p + 8);
                af[mt][3] = *(const uint32_t*)(p + 8 * S + 8);
            }
            uint32_t bf[8][2];
            #pragma unroll
            for (int nt = 0; nt < 8; ++nt) {
                const __half* p = Bs + (b_row0 + nt * 8) * S + kc;
                bf[nt][0] = *(const uint32_t*)(p);
                bf[nt][1] = *(const uint32_t*)(p + 8);
            }
            #pragma unroll
            for (int mt = 0; mt < 4; ++mt)
                #pragma unroll
                for (int nt = 0; nt < 8; ++nt)
                    MMA_F16(acc[mt][nt], af[mt], bf[nt]);
        }
    }

    // ---- epilogue: store partials (padded N => no predication) ----
    float* dst = &g_part[z][0];
    #pragma unroll
    for (int mt = 0; mt < 4; ++mt) {
        const int r0 = m0 + wm * 64 + mt * 16 + g;
        #pragma unroll
        for (int nt = 0; nt < 8; ++nt) {
            const int c = n0 + wn * 64 + nt * 8 + 2 * tig;
            *(float2*)&dst[(size_t)r0 * NPAD + c] =
                make_float2(acc[mt][nt][0], acc[mt][nt][1]);
            *(float2*)&dst[(size_t)(r0 + 8) * NPAD + c] =
                make_float2(acc[mt][nt][2], acc[mt][nt][3]);
        }
    }
    #undef ISSUE
}

// =====================================================================
// Kernel 2: bias + relu + avg-pool(10) + partial sum-of-squares
// grid (4, 32, 10): (channel quarter q, batch b, pool window p)
// =====================================================================
__global__ void __launch_bounds__(256) pool_norm_kernel(const float* __restrict__ conv_b) {
    const int q = blockIdx.x;
    const int b = blockIdx.y;
    const int p = blockIdx.z;
    const int tid = threadIdx.x;
    __shared__ float red[256];

    float ss = 0.f;
    if (tid < 250) {
        const int o = q * 250 + tid;
        const float bias = conv_b[o];
        float acc = 0.f;
        #pragma unroll
        for (int i = 0; i < 10; ++i) {
            const size_t m = (size_t)(b * 100 + p * 10 + i) * NPAD + o;
            float v = g_part[0][m] + g_part[1][m] + g_part[2][m] +
                      g_part[3][m] + g_part[4][m] + bias;
            acc += fmaxf(v, 0.f);
        }
        const float v = acc * 0.1f;
        g_pool[(size_t)b * (NDIM * NPOOL) + o * NPOOL + p] = v;
        ss = v * v;
    }
    red[tid] = ss;
    __syncthreads();
    for (int st = 128; st > 0; st >>= 1) {
        if (tid < st) red[tid] += red[tid + st];
        __syncthreads();
    }
    if (tid == 0) g_ss[b * 40 + q * 10 + p] = red[0];
}

// =====================================================================
// Kernel 3a: fc partials — grid (104, 5), block 256 (8 warps).
// Block (c, z) covers K-slice [z*2000, (z+1)*2000) = 500 float4.
// Warp w handles batches w, w+8, w+16, w+24.
// =====================================================================
__global__ void __launch_bounds__(256) fc_partial_kernel(const float* __restrict__ fc_w) {
    const int c = blockIdx.x;
    const int z = blockIdx.y;
    const int wid = threadIdx.x >> 5;
    const int lane = threadIdx.x & 31;
    const float4* wrow = (const float4*)(fc_w + (size_t)c * (NDIM * NPOOL) + z * 2000);

    #pragma unroll
    for (int bb = 0; bb < 4; ++bb) {
        const int b = wid + bb * 8;
        const float4* pr = (const float4*)(g_pool + (size_t)b * (NDIM * NPOOL) + z * 2000);
        float acc = 0.f;
        #pragma unroll 4
        for (int k = lane; k < 500; k += 32) {
            float4 w4 = wrow[k];
            float4 p4 = pr[k];
            acc += w4.x * p4.x + w4.y * p4.y + w4.z * p4.z + w4.w * p4.w;
        }
        #pragma unroll
        for (int off = 16; off > 0; off >>= 1)
            acc += __shfl_xor_sync(0xFFFFFFFFu, acc, off);
        if (lane == 0) g_fcp[z][b][c] = acc;
    }
}

// =====================================================================
// Kernel 3b: finalize logits (3328 outputs)
// =====================================================================
__global__ void __launch_bounds__(256) fc_final_kernel(const float* __restrict__ fc_b,
                                                       float* __restrict__ out) {
    const int i = blockIdx.x * blockDim.x + threadIdx.x;
    if (i >= BDIM * CDIM) return;
    const int b = i / CDIM;
    const int c = i % CDIM;
    float ss = 0.f;
    #pragma unroll
    for (int j = 0; j < 40; ++j) ss += g_ss[b * 40 + j];
    float dot = 0.f;
    #pragma unroll
    for (int z = 0; z < FCZ; ++z) dot += g_fcp[z][b][c];
    out[i] = fc_b[c] + rsqrtf(1.0f + ss) * dot;
}

// =====================================================================
extern "C" void kernel_launch(void* const* d_in, const int* in_sizes, int n_in,
                              void* d_out, int out_size) {
    const float* x      = (const float*)d_in[0];  // [32,100,30000]
    const float* conv_w = (const float*)d_in[1];  // [1000,30000]
    const float* conv_b = (const float*)d_in[2];  // [1000]
    const float* fc_w   = (const float*)d_in[3];  // [104,10000]
    const float* fc_b   = (const float*)d_in[4];  // [104]
    float* out = (float*)d_out;                   // [32,104]

    static int configured = 0;
    if (!configured) {
        cudaFuncSetAttribute(gemm_kernel,
                             cudaFuncAttributeMaxDynamicSharedMemorySize, SMEM_BYTES);
        configured = 1;
    }

    __half* xh; cudaGetSymbolAddress((void**)&xh, g_xh);
    __half* wh; cudaGetSymbolAddress((void**)&wh, g_wh);

    const int nx8 = (MDIM * KDIM) / 8;
    const int ntot8 = nx8 + (NDIM * KDIM) / 8;
    convert_kernel<<<3072, 256>>>(x, conv_w, xh, wh, nx8, ntot8);
    gemm_kernel<<<dim3(MDIM / MT, 8, KSPLIT), 128, SMEM_BYTES>>>();
    pool_norm_kernel<<<dim3(4, BDIM, NPOOL), 256>>>(conv_b);
    fc_partial_kernel<<<dim3(CDIM, FCZ), 256>>>(fc_w);
    fc_final_kernel<<<(BDIM * CDIM + 255) / 256, 256>>>(fc_b, out);
}

// round 11
// speedup vs baseline: 1.8483x; 1.0544x over previous
#include <cuda_runtime.h>
#include <cuda_fp16.h>
#include <stdint.h>

// ---------------- problem constants ----------------
#define KDIM 30000
#define MDIM 3200            // B*L
#define NDIM 1000            // Co
#define NPAD 1024
#define BDIM 32
#define CDIM 104
#define NPOOL 10
#define FCZ 10               // fc K-split (10000 = 10 * 1000)

// ---------------- GEMM tiling (fp16 mma; A fp32-in-smem w/ consumer cvt) ----
#define MT 128
#define NT 128
#define KB 64                             // k-values per stage
#define KSPLIT 5
#define KLEN (KDIM / KSPLIT)              // 6000
#define ITERS ((KLEN + KB - 1) / KB)      // 94 (tail 48 = full 16B slots both sides)
#define SA 72                             // A row stride in floats  (LDS.64 conflict-free)
#define SB 72                             // B row stride in halves  (LDS.32 conflict-free)
#define A_BYTES (MT * SA * 4)             // 36864
#define B_BYTES (NT * SB * 2)             // 18432
#define STAGE_BYTES (A_BYTES + B_BYTES)   // 55296
#define SMEM_BYTES (2 * STAGE_BYTES)      // 110592 -> occ 2 with 128 threads

// ---------------- static scratch ----------------
__device__ __half g_wh[(size_t)NDIM * KDIM];           // fp16 conv_w (only w converted)
__device__ float g_part[KSPLIT][(size_t)MDIM * NPAD];  // K-split partials
__device__ float g_pool[BDIM * NDIM * NPOOL];
__device__ float g_ss[BDIM * 40];                      // sum-of-squares partials (q,p)
__device__ float g_fcp[FCZ][BDIM][CDIM];               // fc K-split partials

// ---------------- helpers ----------------
static __device__ __forceinline__ uint32_t smem_u32(const void* p) {
    uint32_t a;
    asm("{ .reg .u64 t; cvta.to.shared.u64 t, %1; cvt.u32.u64 %0, t; }" : "=r"(a) : "l"(p));
    return a;
}
static __device__ __forceinline__ void cp_async16(uint32_t saddr, const void* gptr, uint32_t sz) {
    asm volatile("cp.async.cg.shared.global [%0], [%1], 16, %2;"
                 :: "r"(saddr), "l"(gptr), "r"(sz) : "memory");
}
static __device__ __forceinline__ void cp_commit() {
    asm volatile("cp.async.commit_group;" ::: "memory");
}
static __device__ __forceinline__ void cp_wait0() {
    asm volatile("cp.async.wait_group 0;" ::: "memory");
}
// fp32 pair from smem -> packed half2 register (LDS.64 + cvt.rn.f16x2)
static __device__ __forceinline__ uint32_t f2h2(const float* p) {
    float2 v = *(const float2*)p;
    __half2 h = __floats2half2_rn(v.x, v.y);
    return *(uint32_t*)&h;
}

#define MMA_F16(d, a, b)                                                           \
    asm volatile(                                                                  \
        "mma.sync.aligned.m16n8k16.row.col.f32.f16.f16.f32 "                       \
        "{%0,%1,%2,%3}, {%4,%5,%6,%7}, {%8,%9}, {%0,%1,%2,%3};"                    \
        : "+f"((d)[0]), "+f"((d)[1]), "+f"((d)[2]), "+f"((d)[3])                   \
        : "r"((a)[0]), "r"((a)[1]), "r"((a)[2]), "r"((a)[3]),                      \
          "r"((b)[0]), "r"((b)[1]))

// =====================================================================
// Kernel 0: fp32 -> fp16 (rn) for conv_w only (60 MB read / 30 MB write)
// =====================================================================
__global__ void __launch_bounds__(256) convert_w_kernel(const float* __restrict__ w,
                                                        __half* __restrict__ wh, int n8) {
    int i = blockIdx.x * blockDim.x + threadIdx.x;
    const int stride = gridDim.x * blockDim.x;
    for (; i < n8; i += stride) {
        float4 v0 = ((const float4*)w)[i * 2];
        float4 v1 = ((const float4*)w)[i * 2 + 1];
        __half2 h0 = __floats2half2_rn(v0.x, v0.y);
        __half2 h1 = __floats2half2_rn(v0.z, v0.w);
        __half2 h2 = __floats2half2_rn(v1.x, v1.y);
        __half2 h3 = __floats2half2_rn(v1.z, v1.w);
        uint4 o;
        o.x = *(uint32_t*)&h0; o.y = *(uint32_t*)&h1;
        o.z = *(uint32_t*)&h2; o.w = *(uint32_t*)&h3;
        ((uint4*)wh)[i] = o;
    }
}

// =====================================================================
// Kernel 1: GEMM partial[z][m][n] = sum_{k in split z} x[m,k]*w[n,k]
// A: raw fp32 from x via cp.async; fragments converted at LDS time.
// B: fp16 scratch. CTA 128x128, 4 warps of 64x64, 2-stage pipeline.
// grid (25, 8, 5), block 128.
// =====================================================================
__global__ void __launch_bounds__(128, 2)
gemm_kernel(const float* __restrict__ x) {
    extern __shared__ char smem[];
    const int tid = threadIdx.x;
    const int wid = tid >> 5;
    const int lane = tid & 31;
    const int g = lane >> 2;        // groupID
    const int tig = lane & 3;       // thread in group
    const int wm = wid >> 1;        // 0..1
    const int wn = wid & 1;         // 0..1
    const int m0 = blockIdx.x * MT;
    const int n0 = blockIdx.y * NT;
    const int z = blockIdx.z;
    const uint32_t sbase = smem_u32(smem);

    // ---- A addressing: 16 items, row = (tid>>4) + 8u, slot = tid&15 (4 floats) ----
    const int slotA4 = (tid & 15) * 4;
    const float* baseA = x + (size_t)(m0 + (tid >> 4)) * KDIM + (size_t)z * KLEN + slotA4;
    const uint32_t soffA = (uint32_t)((tid >> 4) * (SA * 4) + (tid & 15) * 16);

    // ---- B addressing: 8 items, row = (tid>>3) + 16u, slot = tid&7 (8 halves) ----
    const int slotB8 = (tid & 7) * 8;
    const __half* gpB[8];
    uint32_t okB = 0;
    #pragma unroll
    for (int u = 0; u < 8; ++u) {
        int n = n0 + (tid >> 3) + 16 * u;
        if (n < NDIM) okB |= (1u << u);
        else n = NDIM - 1;
        gpB[u] = g_wh + (size_t)n * KDIM + (size_t)z * KLEN + slotB8;
    }
    const uint32_t soffB = (uint32_t)(A_BYTES + (tid >> 3) * (SB * 2) + (tid & 7) * 16);

    // u-strides in smem bytes: A rows +8 -> 8*288 = 2304; B rows +16 -> 16*144 = 2304
    #define ISSUE(it)                                                              \
        do {                                                                       \
            const int kb = (it) * KB;                                              \
            const int kleft = KLEN - kb;                                           \
            const uint32_t stb = sbase + ((it) & 1) * STAGE_BYTES;                 \
            const uint32_t szA = (slotA4 < kleft) ? 16u : 0u;                      \
            const float* pa = szA ? (baseA + kb) : baseA;  /* clamp OOB tail */    \
            _Pragma("unroll")                                                      \
            for (int u = 0; u < 16; ++u)                                           \
                cp_async16(stb + soffA + u * 2304u, pa + (size_t)u * 8 * KDIM, szA); \
            const uint32_t szB0 = (slotB8 < kleft) ? 16u : 0u;                     \
            _Pragma("unroll")                                                      \
            for (int u = 0; u < 8; ++u) {                                          \
                const uint32_t sz = ((okB >> u) & 1u) ? szB0 : 0u;                 \
                cp_async16(stb + soffB + u * 2304u, gpB[u] + kb, sz);              \
            }                                                                      \
        } while (0)

    // ---- prologue ----
    ISSUE(0); cp_commit();

    // ---- accumulators: warp tile 64x64 = 4x8 mma tiles ----
    float acc[4][8][4];
    #pragma unroll
    for (int mt = 0; mt < 4; ++mt)
        #pragma unroll
        for (int nt = 0; nt < 8; ++nt)
            #pragma unroll
            for (int r = 0; r < 4; ++r) acc[mt][nt][r] = 0.f;

    const int a_row0 = wm * 64 + g;
    const int b_row0 = wn * 64 + g;

    // ---- main loop (2-stage: wait0 -> sync -> issue(it+1) -> compute(it)) ----
    for (int it = 0; it < ITERS; ++it) {
        cp_wait0();
        __syncthreads();
        if (it + 1 < ITERS) { ISSUE(it + 1); }
        cp_commit();

        const float* As = (const float*)(smem + (it & 1) * STAGE_BYTES);
        const __half* Bs = (const __half*)(smem + (it & 1) * STAGE_BYTES + A_BYTES);

        #pragma unroll
        for (int ks = 0; ks < 4; ++ks) {
            const int kc = ks * 16 + 2 * tig;
            uint32_t af[4][4];
            #pragma unroll
            for (int mt = 0; mt < 4; ++mt) {
                const float* p = As + (a_row0 + mt * 16) * SA + kc;
                af[mt][0] = f2h2(p);
                af[mt][1] = f2h2(p + 8 * SA);
                af[mt][2] = f2h2(p + 8);
                af[mt][3] = f2h2(p + 8 * SA + 8);
            }
            uint32_t bf[8][2];
            #pragma unroll
            for (int nt = 0; nt < 8; ++nt) {
                const __half* p = Bs + (b_row0 + nt * 8) * SB + kc;
                bf[nt][0] = *(const uint32_t*)(p);
                bf[nt][1] = *(const uint32_t*)(p + 8);
            }
            #pragma unroll
            for (int mt = 0; mt < 4; ++mt)
                #pragma unroll
                for (int nt = 0; nt < 8; ++nt)
                    MMA_F16(acc[mt][nt], af[mt], bf[nt]);
        }
    }

    // ---- epilogue: store partials (padded N => no predication) ----
    float* dst = &g_part[z][0];
    #pragma unroll
    for (int mt = 0; mt < 4; ++mt) {
        const int r0 = m0 + wm * 64 + mt * 16 + g;
        #pragma unroll
        for (int nt = 0; nt < 8; ++nt) {
            const int c = n0 + wn * 64 + nt * 8 + 2 * tig;
            *(float2*)&dst[(size_t)r0 * NPAD + c] =
                make_float2(acc[mt][nt][0], acc[mt][nt][1]);
            *(float2*)&dst[(size_t)(r0 + 8) * NPAD + c] =
                make_float2(acc[mt][nt][2], acc[mt][nt][3]);
        }
    }
    #undef ISSUE
}

// =====================================================================
// Kernel 2: bias + relu + avg-pool(10) + partial sum-of-squares
// grid (4, 32, 10): (channel quarter q, batch b, pool window p)
// =====================================================================
__global__ void __launch_bounds__(256) pool_norm_kernel(const float* __restrict__ conv_b) {
    const int q = blockIdx.x;
    const int b = blockIdx.y;
    const int p = blockIdx.z;
    const int tid = threadIdx.x;
    __shared__ float red[256];

    float ss = 0.f;
    if (tid < 250) {
        const int o = q * 250 + tid;
        const float bias = conv_b[o];
        float acc = 0.f;
        #pragma unroll
        for (int i = 0; i < 10; ++i) {
            const size_t m = (size_t)(b * 100 + p * 10 + i) * NPAD + o;
            float v = g_part[0][m] + g_part[1][m] + g_part[2][m] +
                      g_part[3][m] + g_part[4][m] + bias;
            acc += fmaxf(v, 0.f);
        }
        const float v = acc * 0.1f;
        g_pool[(size_t)b * (NDIM * NPOOL) + o * NPOOL + p] = v;
        ss = v * v;
    }
    red[tid] = ss;
    __syncthreads();
    for (int st = 128; st > 0; st >>= 1) {
        if (tid < st) red[tid] += red[tid + st];
        __syncthreads();
    }
    if (tid == 0) g_ss[b * 40 + q * 10 + p] = red[0];
}

// =====================================================================
// Kernel 3a: fc partials — grid (104, 10), block 256 (8 warps).
// Block (c, z) covers K-slice [z*1000, (z+1)*1000) = 250 float4.
// =====================================================================
__global__ void __launch_bounds__(256) fc_partial_kernel(const float* __restrict__ fc_w) {
    const int c = blockIdx.x;
    const int z = blockIdx.y;
    const int wid = threadIdx.x >> 5;
    const int lane = threadIdx.x & 31;
    const float4* wrow = (const float4*)(fc_w + (size_t)c * (NDIM * NPOOL) + z * 1000);

    #pragma unroll
    for (int bb = 0; bb < 4; ++bb) {
        const int b = wid + bb * 8;
        const float4* pr = (const float4*)(g_pool + (size_t)b * (NDIM * NPOOL) + z * 1000);
        float acc = 0.f;
        #pragma unroll
        for (int k = lane; k < 250; k += 32) {
            float4 w4 = wrow[k];
            float4 p4 = pr[k];
            acc += w4.x * p4.x + w4.y * p4.y + w4.z * p4.z + w4.w * p4.w;
        }
        #pragma unroll
        for (int off = 16; off > 0; off >>= 1)
            acc += __shfl_xor_sync(0xFFFFFFFFu, acc, off);
        if (lane == 0) g_fcp[z][b][c] = acc;
    }
}

// =====================================================================
// Kernel 3b: finalize logits (3328 outputs)
// =====================================================================
__global__ void __launch_bounds__(256) fc_final_kernel(const float* __restrict__ fc_b,
                                                       float* __restrict__ out) {
    const int i = blockIdx.x * blockDim.x + threadIdx.x;
    if (i >= BDIM * CDIM) return;
    const int b = i / CDIM;
    const int c = i % CDIM;
    float ss = 0.f;
    #pragma unroll
    for (int j = 0; j < 40; ++j) ss += g_ss[b * 40 + j];
    float dot = 0.f;
    #pragma unroll
    for (int z = 0; z < FCZ; ++z) dot += g_fcp[z][b][c];
    out[i] = fc_b[c] + rsqrtf(1.0f + ss) * dot;
}

// =====================================================================
extern "C" void kernel_launch(void* const* d_in, const int* in_sizes, int n_in,
                              void* d_out, int out_size) {
    const float* x      = (const float*)d_in[0];  // [32,100,30000]
    const float* conv_w = (const float*)d_in[1];  // [1000,30000]
    const float* conv_b = (const float*)d_in[2];  // [1000]
    const float* fc_w   = (const float*)d_in[3];  // [104,10000]
    const float* fc_b   = (const float*)d_in[4];  // [104]
    float* out = (float*)d_out;                   // [32,104]

    static int configured = 0;
    if (!configured) {
        cudaFuncSetAttribute(gemm_kernel,
                             cudaFuncAttributeMaxDynamicSharedMemorySize, SMEM_BYTES);
        configured = 1;
    }

    __half* wh; cudaGetSymbolAddress((void**)&wh, g_wh);

    convert_w_kernel<<<1024, 256>>>(conv_w, wh, (NDIM * KDIM) / 8);
    gemm_kernel<<<dim3(MDIM / MT, 8, KSPLIT), 128, SMEM_BYTES>>>(x);
    pool_norm_kernel<<<dim3(4, BDIM, NPOOL), 256>>>(conv_b);
    fc_partial_kernel<<<dim3(CDIM, FCZ), 256>>>(fc_w);
    fc_final_kernel<<<(BDIM * CDIM + 255) / 256, 256>>>(fc_b, out);
}